// round 1
// baseline (speedup 1.0000x reference)
#include <cuda_runtime.h>
#include <math.h>

#define BB 8
#define CC 128
#define HH 128
#define WW 128
#define NHH 4
#define HDD 32
#define SG2 256
#define HWP (HH*WW)      // 16384
#define NPIX (BB*HWP)    // 131072
#define KK2 25
#define SCALE 0.17677669529663687f   // 1/sqrt(32)

// ---- scratch (static device arrays; no runtime allocation) ----
static __device__ float g_q[(size_t)NPIX*CC];    // [(b*NH+h)*HW + ij]*HD + d
static __device__ float g_k[(size_t)NPIX*CC];
static __device__ float g_v[(size_t)NPIX*CC];
static __device__ float g_pwd[(size_t)NPIX*KK2]; // [p*25 + k]
static __device__ float g_agg[(size_t)NPIX*CC];  // [p*128 + c]

// ============================================================
// Kernel 1: QKV GEMM.  out[p, n] = sum_c x[b,c,ij] * W[c,n] + bias[n]
// W = concat(w_qk [128x256], w_v [128x128]) -> N=384
// Tiles: 64 pixels x 64 outputs, K=128 fully resident in smem.
// ============================================================
__global__ void __launch_bounds__(256)
k_qkv(const float* __restrict__ x, const float* __restrict__ w_qk,
      const float* __restrict__ b_qk, const float* __restrict__ w_v,
      const float* __restrict__ b_v)
{
    extern __shared__ float sm[];
    float* As = sm;             // [128][64]  (k-major: natural from BCHW x)
    float* Bs = sm + 128*64;    // [128][64]

    const int tid = threadIdx.x;
    const int p0  = blockIdx.x * 64;   // 64-pixel tile never crosses batch (16384 % 64 == 0)
    const int n0  = blockIdx.y * 64;
    const int b   = p0 / HWP;
    const int ij0 = p0 % HWP;

    const float* xb = x + (size_t)b*CC*HWP + ij0;
#pragma unroll
    for (int it = 0; it < 8; it++) {
        int idx = tid + it*256;        // 2048 float4 slots
        int k = idx >> 4, mv = idx & 15;
        *(float4*)(As + k*64 + mv*4) = *(const float4*)(xb + (size_t)k*HWP + mv*4);
    }
    if (n0 < 2*CC) {
#pragma unroll
        for (int it = 0; it < 8; it++) {
            int idx = tid + it*256;
            int k = idx >> 4, nv = idx & 15;
            *(float4*)(Bs + k*64 + nv*4) = *(const float4*)(w_qk + k*2*CC + n0 + nv*4);
        }
    } else {
#pragma unroll
        for (int it = 0; it < 8; it++) {
            int idx = tid + it*256;
            int k = idx >> 4, nv = idx & 15;
            *(float4*)(Bs + k*64 + nv*4) = *(const float4*)(w_v + k*CC + (n0 - 2*CC) + nv*4);
        }
    }
    __syncthreads();

    const int tx = tid & 15, ty = tid >> 4;
    float acc[4][4];
#pragma unroll
    for (int i=0;i<4;i++)
#pragma unroll
        for (int j=0;j<4;j++) acc[i][j] = 0.f;

#pragma unroll 8
    for (int k = 0; k < CC; k++) {
        float4 a4 = *(const float4*)(As + k*64 + ty*4);
        float4 b4 = *(const float4*)(Bs + k*64 + tx*4);
        float av[4] = {a4.x, a4.y, a4.z, a4.w};
        float bw[4] = {b4.x, b4.y, b4.z, b4.w};
#pragma unroll
        for (int i=0;i<4;i++)
#pragma unroll
            for (int j=0;j<4;j++)
                acc[i][j] = fmaf(av[i], bw[j], acc[i][j]);
    }

    const int ng = n0 + tx*4;
    float bias[4];
#pragma unroll
    for (int j=0;j<4;j++)
        bias[j] = (ng < 2*CC) ? b_qk[ng+j] : b_v[ng - 2*CC + j];

    float* dst; int within;
    if (ng < CC)        { dst = g_q; within = ng; }
    else if (ng < 2*CC) { dst = g_k; within = ng - CC; }
    else                { dst = g_v; within = ng - 2*CC; }
    const int head = within >> 5, d0 = within & 31;

#pragma unroll
    for (int mi=0; mi<4; mi++) {
        int ij = ij0 + ty*4 + mi;
        float4 o = make_float4(acc[mi][0]+bias[0], acc[mi][1]+bias[1],
                               acc[mi][2]+bias[2], acc[mi][3]+bias[3]);
        *(float4*)(dst + ((size_t)(b*NHH + head)*HWP + ij)*HDD + d0) = o;
    }
}

// ============================================================
// Kernel 2: pwd[p, k] = sum_s sims[p,s] * sims[p+off_k, s]
// Block = 8x32 pixel tile, 12x36 halo, 32-channel chunks of the
// 256 superpixel dims resident in smem (stride 36 -> conflict-free).
// ============================================================
__global__ void __launch_bounds__(256)
k_pwd(const float* __restrict__ sims)
{
    extern __shared__ float Ss[];  // [432 halo pixels][36 (32ch + pad)]
    const int b  = blockIdx.z;
    const int i0 = blockIdx.y * 8;
    const int j0 = blockIdx.x * 32;
    const int tx = threadIdx.x, ty = threadIdx.y;
    const int tid = ty*32 + tx;
    const float* sb = sims + (size_t)b*HWP*SG2;

    float acc[KK2];
#pragma unroll
    for (int k=0;k<KK2;k++) acc[k] = 0.f;

    for (int scc = 0; scc < SG2; scc += 32) {
        __syncthreads();
        for (int idx = tid; idx < 432*8; idx += 256) {
            int pix = idx >> 3, v = idx & 7;
            int hr = pix / 36, hc = pix - hr*36;
            int gi = i0 - 2 + hr, gj = j0 - 2 + hc;
            float4 val = make_float4(0.f,0.f,0.f,0.f);
            if ((unsigned)gi < HH && (unsigned)gj < WW)
                val = *(const float4*)(sb + ((size_t)gi*WW + gj)*SG2 + scc + v*4);
            *(float4*)(Ss + pix*36 + v*4) = val;
        }
        __syncthreads();

        float own[32];
        const float* op = Ss + ((ty+2)*36 + (tx+2))*36;
#pragma unroll
        for (int v=0; v<8; v++) {
            float4 t = *(const float4*)(op + v*4);
            own[v*4]=t.x; own[v*4+1]=t.y; own[v*4+2]=t.z; own[v*4+3]=t.w;
        }
#pragma unroll
        for (int di=0; di<5; di++) {
#pragma unroll
            for (int dj=0; dj<5; dj++) {
                const float* np = Ss + ((ty+di)*36 + (tx+dj))*36;
                float s = 0.f;
#pragma unroll
                for (int v=0; v<8; v++) {
                    float4 t = *(const float4*)(np + v*4);
                    s = fmaf(own[v*4],   t.x, s);
                    s = fmaf(own[v*4+1], t.y, s);
                    s = fmaf(own[v*4+2], t.z, s);
                    s = fmaf(own[v*4+3], t.w, s);
                }
                acc[di*5+dj] += s;
            }
        }
    }
    const size_t p = (size_t)b*HWP + (size_t)(i0+ty)*WW + (j0+tx);
#pragma unroll
    for (int k=0;k<KK2;k++) g_pwd[p*KK2 + k] = acc[k];
}

// ============================================================
// Kernel 3: scores -> exp -> *pwd -> renorm -> V aggregation.
// Softmax denominator cancels against the pwd renorm, so we use
// w_k = exp(s_k - max) * pwd_k and divide by its sum once.
// Same 8x32 tile / 12x36 halo; K and V share one smem buffer.
// ============================================================
__global__ void __launch_bounds__(256)
k_attn()
{
    extern __shared__ float Ts[];  // [432][36]
    const int bh = blockIdx.z;          // b*NH + h
    const int b  = bh >> 2;
    const int h  = bh & 3;
    const int i0 = blockIdx.y * 8;
    const int j0 = blockIdx.x * 32;
    const int tx = threadIdx.x, ty = threadIdx.y;
    const int tid = ty*32 + tx;
    const size_t headoff = (size_t)bh*HWP*HDD;
    const int ij = (i0+ty)*WW + (j0+tx);

    float q[32];
    {
        const float* qp = g_q + headoff + (size_t)ij*HDD;
#pragma unroll
        for (int v=0; v<8; v++) {
            float4 t = *(const float4*)(qp + v*4);
            q[v*4]=t.x; q[v*4+1]=t.y; q[v*4+2]=t.z; q[v*4+3]=t.w;
        }
    }

    // --- K halo ---
    const float* kb = g_k + headoff;
    for (int idx = tid; idx < 432*8; idx += 256) {
        int pix = idx >> 3, v = idx & 7;
        int hr = pix / 36, hc = pix - hr*36;
        int gi = i0 - 2 + hr, gj = j0 - 2 + hc;
        float4 val = make_float4(0.f,0.f,0.f,0.f);
        if ((unsigned)gi < HH && (unsigned)gj < WW)
            val = *(const float4*)(kb + (size_t)(gi*WW + gj)*HDD + v*4);
        *(float4*)(Ts + pix*36 + v*4) = val;
    }
    __syncthreads();

    float sc[KK2];
#pragma unroll
    for (int di=0; di<5; di++) {
#pragma unroll
        for (int dj=0; dj<5; dj++) {
            const float* np = Ts + ((ty+di)*36 + (tx+dj))*36;
            float s = 0.f;
#pragma unroll
            for (int v=0; v<8; v++) {
                float4 t = *(const float4*)(np + v*4);
                s = fmaf(q[v*4],   t.x, s);
                s = fmaf(q[v*4+1], t.y, s);
                s = fmaf(q[v*4+2], t.z, s);
                s = fmaf(q[v*4+3], t.w, s);
            }
            sc[di*5+dj] = s * SCALE;
        }
    }
    __syncthreads();   // done reading K from Ts

    // --- V halo (reuse Ts) ---
    const float* vb = g_v + headoff;
    for (int idx = tid; idx < 432*8; idx += 256) {
        int pix = idx >> 3, v = idx & 7;
        int hr = pix / 36, hc = pix - hr*36;
        int gi = i0 - 2 + hr, gj = j0 - 2 + hc;
        float4 val = make_float4(0.f,0.f,0.f,0.f);
        if ((unsigned)gi < HH && (unsigned)gj < WW)
            val = *(const float4*)(vb + (size_t)(gi*WW + gj)*HDD + v*4);
        *(float4*)(Ts + pix*36 + v*4) = val;
    }

    // weights (registers only, overlaps the V loads)
    float m = sc[0];
#pragma unroll
    for (int k=1;k<KK2;k++) m = fmaxf(m, sc[k]);
    const float* pw = g_pwd + ((size_t)b*HWP + ij)*KK2;
    float w[KK2]; float ssum = 0.f;
#pragma unroll
    for (int k=0;k<KK2;k++) { w[k] = __expf(sc[k]-m) * pw[k]; ssum += w[k]; }
    const float inv = 1.f / fmaxf(ssum, 1e-30f);

    __syncthreads();   // V resident

    float out[32];
#pragma unroll
    for (int v=0;v<32;v++) out[v] = 0.f;
#pragma unroll
    for (int di=0; di<5; di++) {
#pragma unroll
        for (int dj=0; dj<5; dj++) {
            float wk = w[di*5+dj] * inv;
            const float* np = Ts + ((ty+di)*36 + (tx+dj))*36;
#pragma unroll
            for (int v=0; v<8; v++) {
                float4 t = *(const float4*)(np + v*4);
                out[v*4]   = fmaf(wk, t.x, out[v*4]);
                out[v*4+1] = fmaf(wk, t.y, out[v*4+1]);
                out[v*4+2] = fmaf(wk, t.z, out[v*4+2]);
                out[v*4+3] = fmaf(wk, t.w, out[v*4+3]);
            }
        }
    }
    float* ag = g_agg + ((size_t)b*HWP + ij)*CC + h*HDD;
#pragma unroll
    for (int v=0; v<8; v++)
        *(float4*)(ag + v*4) = make_float4(out[v*4], out[v*4+1], out[v*4+2], out[v*4+3]);
}

// ============================================================
// Kernel 4: proj GEMM + BCHW transpose store.
// out[b, oc, ij] = sum_c agg[p,c] * w_proj[c,oc] + b_proj[oc]
// ============================================================
__global__ void __launch_bounds__(256)
k_proj(const float* __restrict__ w_proj, const float* __restrict__ b_proj,
       float* __restrict__ out)
{
    extern __shared__ float sm[];
    float* As = sm;             // [64][132]  (m-major, padded)
    float* Bs = sm + 64*132;    // [128][64]

    const int tid = threadIdx.x;
    const int p0  = blockIdx.x * 64;
    const int n0  = blockIdx.y * 64;
    const int b   = p0 / HWP;
    const int ij0 = p0 % HWP;

#pragma unroll
    for (int it=0; it<8; it++) {
        int idx = tid + it*256;        // 2048 float4
        int m = idx >> 5, cv = idx & 31;
        *(float4*)(As + m*132 + cv*4) = *(const float4*)(g_agg + (size_t)(p0+m)*CC + cv*4);
    }
#pragma unroll
    for (int it=0; it<8; it++) {
        int idx = tid + it*256;
        int k = idx >> 4, nv = idx & 15;
        *(float4*)(Bs + k*64 + nv*4) = *(const float4*)(w_proj + k*CC + n0 + nv*4);
    }
    __syncthreads();

    const int tx = tid & 15, ty = tid >> 4;
    float acc[4][4];
#pragma unroll
    for (int i=0;i<4;i++)
#pragma unroll
        for (int j=0;j<4;j++) acc[i][j] = 0.f;

#pragma unroll 8
    for (int k=0; k<CC; k++) {
        float4 b4 = *(const float4*)(Bs + k*64 + tx*4);
        float bw[4] = {b4.x, b4.y, b4.z, b4.w};
        float av[4];
#pragma unroll
        for (int mi=0; mi<4; mi++) av[mi] = As[(ty*4+mi)*132 + k];
#pragma unroll
        for (int i=0;i<4;i++)
#pragma unroll
            for (int j=0;j<4;j++)
                acc[i][j] = fmaf(av[i], bw[j], acc[i][j]);
    }

    float* ob = out + (size_t)b*CC*HWP + ij0 + ty*4;
#pragma unroll
    for (int ni=0; ni<4; ni++) {
        int oc = n0 + tx*4 + ni;
        float bv = b_proj[oc];
        float4 o = make_float4(acc[0][ni]+bv, acc[1][ni]+bv,
                               acc[2][ni]+bv, acc[3][ni]+bv);
        *(float4*)(ob + (size_t)oc*HWP) = o;
    }
}

// ============================================================
extern "C" void kernel_launch(void* const* d_in, const int* in_sizes, int n_in,
                              void* d_out, int out_size)
{
    const float* x      = (const float*)d_in[0];
    const float* sims   = (const float*)d_in[1];
    const float* w_qk   = (const float*)d_in[2];
    const float* b_qk   = (const float*)d_in[3];
    const float* w_v    = (const float*)d_in[4];
    const float* b_v    = (const float*)d_in[5];
    const float* w_proj = (const float*)d_in[6];
    const float* b_proj = (const float*)d_in[7];
    float* out = (float*)d_out;

    // idempotent attribute sets (not stream ops; capture-safe)
    cudaFuncSetAttribute(k_qkv,  cudaFuncAttributeMaxDynamicSharedMemorySize, 128*64*2*4);
    cudaFuncSetAttribute(k_pwd,  cudaFuncAttributeMaxDynamicSharedMemorySize, 432*36*4);
    cudaFuncSetAttribute(k_attn, cudaFuncAttributeMaxDynamicSharedMemorySize, 432*36*4);
    cudaFuncSetAttribute(k_proj, cudaFuncAttributeMaxDynamicSharedMemorySize, (64*132 + 128*64)*4);

    k_qkv <<<dim3(NPIX/64, 6),        256,        128*64*2*4>>>(x, w_qk, b_qk, w_v, b_v);
    k_pwd <<<dim3(WW/32, HH/8, BB),   dim3(32,8), 432*36*4>>>(sims);
    k_attn<<<dim3(WW/32, HH/8, BB*NHH), dim3(32,8), 432*36*4>>>();
    k_proj<<<dim3(NPIX/64, 2),        256,        (64*132 + 128*64)*4>>>(w_proj, b_proj, out);
}

// round 3
// speedup vs baseline: 1.2600x; 1.2600x over previous
#include <cuda_runtime.h>
#include <mma.h>
#include <math.h>

using namespace nvcuda;

#define BB 8
#define CC 128
#define HH 128
#define WW 128
#define NHH 4
#define HDD 32
#define SG2 256
#define HWP (HH*WW)      // 16384
#define NPIX (BB*HWP)    // 131072
#define KK2 25
#define SCALE 0.17677669529663687f   // 1/sqrt(32)

// ---- scratch (static device arrays; no runtime allocation) ----
static __device__ float g_q[(size_t)NPIX*CC];    // [(b*NH+h)*HW + ij]*HD + d
static __device__ float g_k[(size_t)NPIX*CC];
static __device__ float g_v[(size_t)NPIX*CC];
static __device__ float g_pwd[(size_t)NPIX*KK2]; // [p*25 + k]
static __device__ float g_agg[(size_t)NPIX*CC];  // [p*128 + c]

#define GEMM_SMEM ((16*132 + 128*132)*4)

// ============================================================
// Kernel 1: QKV GEMM via WMMA tf32.
// out[p, n] = sum_c x[b,c,ij]*W[c,n] + bias[n], N-tiles: q(128)|k(128)|v(128)
// A: directly from global x — BCHW is col_major(m=pixel, k=channel), ld=HWP.
// B: staged in smem row_major [k][n], ld=132.
// Bias: pre-loaded into accumulator fragments from a replicated smem tile.
// D: stored straight into g_q/g_k/g_v ([pix][head-dim] row_major, ld=32).
// ============================================================
__global__ void __launch_bounds__(256, 2)
k_qkv_wmma(const float* __restrict__ x, const float* __restrict__ w_qk,
           const float* __restrict__ b_qk, const float* __restrict__ w_v,
           const float* __restrict__ b_v)
{
    extern __shared__ float sm[];
    float* bias_s = sm;             // [16][132] (rows identical)
    float* Bs     = sm + 16*132;    // [128][132] row-major (k, n)

    const int tid = threadIdx.x;
    const int wid = tid >> 5;
    const int wm  = wid & 3;        // m quarter  (32 pixels)
    const int wn  = wid >> 2;       // n half     (64 outputs)
    const int p0  = blockIdx.x * 128;
    const int b   = p0 / HWP;
    const int ij0 = p0 % HWP;
    const float* xb = x + (size_t)b*CC*HWP + ij0;

    for (int nt = 0; nt < 3; nt++) {
        __syncthreads();   // protect Bs/bias_s from previous iteration readers
#pragma unroll
        for (int it = 0; it < 16; it++) {
            int idx = tid + it*256;            // 4096 float4
            int k = idx >> 5, n4 = idx & 31;
            const float* src = (nt < 2) ? (w_qk + k*2*CC + nt*128 + n4*4)
                                        : (w_v  + k*CC  + n4*4);
            *(float4*)(Bs + k*132 + n4*4) = *(const float4*)src;
        }
        if (tid < 128) {
            float bv = (nt < 2) ? b_qk[nt*128 + tid] : b_v[tid];
#pragma unroll
            for (int r = 0; r < 16; r++) bias_s[r*132 + tid] = bv;
        }
        __syncthreads();

        wmma::fragment<wmma::accumulator, 16,16,8, float> acc[2][4];
#pragma unroll
        for (int mi = 0; mi < 2; mi++)
#pragma unroll
            for (int ni = 0; ni < 4; ni++)
                wmma::load_matrix_sync(acc[mi][ni], bias_s + wn*64 + ni*16,
                                       132, wmma::mem_row_major);

#pragma unroll
        for (int k0 = 0; k0 < CC; k0 += 8) {
            wmma::fragment<wmma::matrix_a, 16,16,8, wmma::precision::tf32,
                           wmma::col_major> a[2];
#pragma unroll
            for (int mi = 0; mi < 2; mi++) {
                wmma::load_matrix_sync(a[mi],
                    xb + (size_t)k0*HWP + (wm*32 + mi*16), HWP);
#pragma unroll
                for (int e = 0; e < a[mi].num_elements; e++)
                    a[mi].x[e] = wmma::__float_to_tf32(a[mi].x[e]);
            }
            wmma::fragment<wmma::matrix_b, 16,16,8, wmma::precision::tf32,
                           wmma::row_major> bf[4];
#pragma unroll
            for (int ni = 0; ni < 4; ni++) {
                wmma::load_matrix_sync(bf[ni], Bs + k0*132 + wn*64 + ni*16, 132);
#pragma unroll
                for (int e = 0; e < bf[ni].num_elements; e++)
                    bf[ni].x[e] = wmma::__float_to_tf32(bf[ni].x[e]);
            }
#pragma unroll
            for (int mi = 0; mi < 2; mi++)
#pragma unroll
                for (int ni = 0; ni < 4; ni++)
                    wmma::mma_sync(acc[mi][ni], a[mi], bf[ni], acc[mi][ni]);
        }

        float* dstbase = (nt == 0) ? g_q : (nt == 1) ? g_k : g_v;
#pragma unroll
        for (int mi = 0; mi < 2; mi++)
#pragma unroll
            for (int ni = 0; ni < 4; ni++) {
                int n0 = wn*64 + ni*16;
                int head = n0 >> 5, d0 = n0 & 31;
                float* dst = dstbase +
                    ((size_t)(b*NHH + head)*HWP + ij0 + wm*32 + mi*16)*HDD + d0;
                wmma::store_matrix_sync(dst, acc[mi][ni], HDD, wmma::mem_row_major);
            }
    }
}

// ============================================================
// Kernel 2: pwd[p, k] = sum_s sims[p,s] * sims[p+off_k, s]
// ============================================================
__global__ void __launch_bounds__(256)
k_pwd(const float* __restrict__ sims)
{
    extern __shared__ float Ss[];  // [432 halo pixels][36]
    const int b  = blockIdx.z;
    const int i0 = blockIdx.y * 8;
    const int j0 = blockIdx.x * 32;
    const int tx = threadIdx.x, ty = threadIdx.y;
    const int tid = ty*32 + tx;
    const float* sb = sims + (size_t)b*HWP*SG2;

    float acc[KK2];
#pragma unroll
    for (int k=0;k<KK2;k++) acc[k] = 0.f;

    for (int scc = 0; scc < SG2; scc += 32) {
        __syncthreads();
        for (int idx = tid; idx < 432*8; idx += 256) {
            int pix = idx >> 3, v = idx & 7;
            int hr = pix / 36, hc = pix - hr*36;
            int gi = i0 - 2 + hr, gj = j0 - 2 + hc;
            float4 val = make_float4(0.f,0.f,0.f,0.f);
            if ((unsigned)gi < HH && (unsigned)gj < WW)
                val = *(const float4*)(sb + ((size_t)gi*WW + gj)*SG2 + scc + v*4);
            *(float4*)(Ss + pix*36 + v*4) = val;
        }
        __syncthreads();

        float own[32];
        const float* op = Ss + ((ty+2)*36 + (tx+2))*36;
#pragma unroll
        for (int v=0; v<8; v++) {
            float4 t = *(const float4*)(op + v*4);
            own[v*4]=t.x; own[v*4+1]=t.y; own[v*4+2]=t.z; own[v*4+3]=t.w;
        }
#pragma unroll
        for (int di=0; di<5; di++) {
#pragma unroll
            for (int dj=0; dj<5; dj++) {
                const float* np = Ss + ((ty+di)*36 + (tx+dj))*36;
                float s = 0.f;
#pragma unroll
                for (int v=0; v<8; v++) {
                    float4 t = *(const float4*)(np + v*4);
                    s = fmaf(own[v*4],   t.x, s);
                    s = fmaf(own[v*4+1], t.y, s);
                    s = fmaf(own[v*4+2], t.z, s);
                    s = fmaf(own[v*4+3], t.w, s);
                }
                acc[di*5+dj] += s;
            }
        }
    }
    const size_t p = (size_t)b*HWP + (size_t)(i0+ty)*WW + (j0+tx);
#pragma unroll
    for (int k=0;k<KK2;k++) g_pwd[p*KK2 + k] = acc[k];
}

// ============================================================
// Kernel 3: scores -> exp -> *pwd -> renorm -> V aggregation.
// Softmax denominator cancels against pwd renorm.
// ============================================================
__global__ void __launch_bounds__(256)
k_attn()
{
    extern __shared__ float Ts[];  // [432][36]
    const int bh = blockIdx.z;
    const int b  = bh >> 2;
    const int h  = bh & 3;
    const int i0 = blockIdx.y * 8;
    const int j0 = blockIdx.x * 32;
    const int tx = threadIdx.x, ty = threadIdx.y;
    const int tid = ty*32 + tx;
    const size_t headoff = (size_t)bh*HWP*HDD;
    const int ij = (i0+ty)*WW + (j0+tx);

    float q[32];
    {
        const float* qp = g_q + headoff + (size_t)ij*HDD;
#pragma unroll
        for (int v=0; v<8; v++) {
            float4 t = *(const float4*)(qp + v*4);
            q[v*4]=t.x; q[v*4+1]=t.y; q[v*4+2]=t.z; q[v*4+3]=t.w;
        }
    }

    const float* kb = g_k + headoff;
    for (int idx = tid; idx < 432*8; idx += 256) {
        int pix = idx >> 3, v = idx & 7;
        int hr = pix / 36, hc = pix - hr*36;
        int gi = i0 - 2 + hr, gj = j0 - 2 + hc;
        float4 val = make_float4(0.f,0.f,0.f,0.f);
        if ((unsigned)gi < HH && (unsigned)gj < WW)
            val = *(const float4*)(kb + (size_t)(gi*WW + gj)*HDD + v*4);
        *(float4*)(Ts + pix*36 + v*4) = val;
    }
    __syncthreads();

    float sc[KK2];
#pragma unroll
    for (int di=0; di<5; di++) {
#pragma unroll
        for (int dj=0; dj<5; dj++) {
            const float* np = Ts + ((ty+di)*36 + (tx+dj))*36;
            float s = 0.f;
#pragma unroll
            for (int v=0; v<8; v++) {
                float4 t = *(const float4*)(np + v*4);
                s = fmaf(q[v*4],   t.x, s);
                s = fmaf(q[v*4+1], t.y, s);
                s = fmaf(q[v*4+2], t.z, s);
                s = fmaf(q[v*4+3], t.w, s);
            }
            sc[di*5+dj] = s * SCALE;
        }
    }
    __syncthreads();

    const float* vb = g_v + headoff;
    for (int idx = tid; idx < 432*8; idx += 256) {
        int pix = idx >> 3, v = idx & 7;
        int hr = pix / 36, hc = pix - hr*36;
        int gi = i0 - 2 + hr, gj = j0 - 2 + hc;
        float4 val = make_float4(0.f,0.f,0.f,0.f);
        if ((unsigned)gi < HH && (unsigned)gj < WW)
            val = *(const float4*)(vb + (size_t)(gi*WW + gj)*HDD + v*4);
        *(float4*)(Ts + pix*36 + v*4) = val;
    }

    float m = sc[0];
#pragma unroll
    for (int k=1;k<KK2;k++) m = fmaxf(m, sc[k]);
    const float* pw = g_pwd + ((size_t)b*HWP + ij)*KK2;
    float w[KK2]; float ssum = 0.f;
#pragma unroll
    for (int k=0;k<KK2;k++) { w[k] = __expf(sc[k]-m) * pw[k]; ssum += w[k]; }
    const float inv = 1.f / fmaxf(ssum, 1e-30f);

    __syncthreads();

    float out[32];
#pragma unroll
    for (int v=0;v<32;v++) out[v] = 0.f;
#pragma unroll
    for (int di=0; di<5; di++) {
#pragma unroll
        for (int dj=0; dj<5; dj++) {
            float wk = w[di*5+dj] * inv;
            const float* np = Ts + ((ty+di)*36 + (tx+dj))*36;
#pragma unroll
            for (int v=0; v<8; v++) {
                float4 t = *(const float4*)(np + v*4);
                out[v*4]   = fmaf(wk, t.x, out[v*4]);
                out[v*4+1] = fmaf(wk, t.y, out[v*4+1]);
                out[v*4+2] = fmaf(wk, t.z, out[v*4+2]);
                out[v*4+3] = fmaf(wk, t.w, out[v*4+3]);
            }
        }
    }
    float* ag = g_agg + ((size_t)b*HWP + ij)*CC + h*HDD;
#pragma unroll
    for (int v=0; v<8; v++)
        *(float4*)(ag + v*4) = make_float4(out[v*4], out[v*4+1],
                                           out[v*4+2], out[v*4+3]);
}

// ============================================================
// Kernel 4: proj GEMM via WMMA tf32 + free BCHW transpose.
// A: g_agg row_major(m=pixel, k=channel), ld=128, direct from global.
// B: w_proj staged in smem row_major [k][n], ld=132.
// D: stored col_major with ld=HWP -> lands directly in BCHW layout.
// ============================================================
__global__ void __launch_bounds__(256, 2)
k_proj_wmma(const float* __restrict__ w_proj, const float* __restrict__ b_proj,
            float* __restrict__ out)
{
    extern __shared__ float sm[];
    float* bias_s = sm;             // [16][132]
    float* Bs     = sm + 16*132;    // [128][132]

    const int tid = threadIdx.x;
    const int wid = tid >> 5;
    const int wm  = wid & 3;
    const int wn  = wid >> 2;
    const int p0  = blockIdx.x * 128;
    const int b   = p0 / HWP;
    const int ij0 = p0 % HWP;

#pragma unroll
    for (int it = 0; it < 16; it++) {
        int idx = tid + it*256;
        int k = idx >> 5, n4 = idx & 31;
        *(float4*)(Bs + k*132 + n4*4) = *(const float4*)(w_proj + k*CC + n4*4);
    }
    if (tid < 128) {
        float bv = b_proj[tid];
#pragma unroll
        for (int r = 0; r < 16; r++) bias_s[r*132 + tid] = bv;
    }
    __syncthreads();

    wmma::fragment<wmma::accumulator, 16,16,8, float> acc[2][4];
#pragma unroll
    for (int mi = 0; mi < 2; mi++)
#pragma unroll
        for (int ni = 0; ni < 4; ni++)
            wmma::load_matrix_sync(acc[mi][ni], bias_s + wn*64 + ni*16,
                                   132, wmma::mem_row_major);

    const float* ab = g_agg + (size_t)p0 * CC;
#pragma unroll
    for (int k0 = 0; k0 < CC; k0 += 8) {
        wmma::fragment<wmma::matrix_a, 16,16,8, wmma::precision::tf32,
                       wmma::row_major> a[2];
#pragma unroll
        for (int mi = 0; mi < 2; mi++) {
            wmma::load_matrix_sync(a[mi], ab + (size_t)(wm*32 + mi*16)*CC + k0, CC);
#pragma unroll
            for (int e = 0; e < a[mi].num_elements; e++)
                a[mi].x[e] = wmma::__float_to_tf32(a[mi].x[e]);
        }
        wmma::fragment<wmma::matrix_b, 16,16,8, wmma::precision::tf32,
                       wmma::row_major> bf[4];
#pragma unroll
        for (int ni = 0; ni < 4; ni++) {
            wmma::load_matrix_sync(bf[ni], Bs + k0*132 + wn*64 + ni*16, 132);
#pragma unroll
            for (int e = 0; e < bf[ni].num_elements; e++)
                bf[ni].x[e] = wmma::__float_to_tf32(bf[ni].x[e]);
        }
#pragma unroll
        for (int mi = 0; mi < 2; mi++)
#pragma unroll
            for (int ni = 0; ni < 4; ni++)
                wmma::mma_sync(acc[mi][ni], a[mi], bf[ni], acc[mi][ni]);
    }

    float* ob = out + (size_t)b*CC*HWP + ij0;
#pragma unroll
    for (int mi = 0; mi < 2; mi++)
#pragma unroll
        for (int ni = 0; ni < 4; ni++) {
            int n0 = wn*64 + ni*16;
            int m0 = wm*32 + mi*16;
            wmma::store_matrix_sync(ob + (size_t)n0*HWP + m0, acc[mi][ni],
                                    HWP, wmma::mem_col_major);
        }
}

// ============================================================
extern "C" void kernel_launch(void* const* d_in, const int* in_sizes, int n_in,
                              void* d_out, int out_size)
{
    const float* x      = (const float*)d_in[0];
    const float* sims   = (const float*)d_in[1];
    const float* w_qk   = (const float*)d_in[2];
    const float* b_qk   = (const float*)d_in[3];
    const float* w_v    = (const float*)d_in[4];
    const float* b_v    = (const float*)d_in[5];
    const float* w_proj = (const float*)d_in[6];
    const float* b_proj = (const float*)d_in[7];
    float* out = (float*)d_out;

    cudaFuncSetAttribute(k_qkv_wmma,  cudaFuncAttributeMaxDynamicSharedMemorySize, GEMM_SMEM);
    cudaFuncSetAttribute(k_pwd,       cudaFuncAttributeMaxDynamicSharedMemorySize, 432*36*4);
    cudaFuncSetAttribute(k_attn,      cudaFuncAttributeMaxDynamicSharedMemorySize, 432*36*4);
    cudaFuncSetAttribute(k_proj_wmma, cudaFuncAttributeMaxDynamicSharedMemorySize, GEMM_SMEM);

    k_qkv_wmma <<<NPIX/128, 256, GEMM_SMEM>>>(x, w_qk, b_qk, w_v, b_v);
    k_pwd      <<<dim3(WW/32, HH/8, BB),     dim3(32,8), 432*36*4>>>(sims);
    k_attn     <<<dim3(WW/32, HH/8, BB*NHH), dim3(32,8), 432*36*4>>>();
    k_proj_wmma<<<NPIX/128, 256, GEMM_SMEM>>>(w_proj, b_proj, out);
}